// round 10
// baseline (speedup 1.0000x reference)
#include <cuda_runtime.h>

#define S 32
#define NMAX 204800
#define MMAX 2048

#define GX 38
#define NC (GX * GX)
#define CELL 4.0f
#define ORG (-76.0f)
#define CBITS 11
#define CMASK ((1 << CBITS) - 1)
#define HITCAP 2048
#define NWORDS ((NMAX + 31) / 32)

// ---------------- scratch (no allocations allowed) ----------------
__device__ float2 g_xy[NMAX];
__device__ unsigned g_bits[NWORDS];   // flag bitmask (zero-init; k_fill re-clears)
__device__ int    g_wrank[NWORDS];    // exclusive popc prefix per word
__device__ int    g_sidx[MMAX * S];
__device__ int    g_scount[MMAX];
__device__ int    g_cell[NMAX];       // packed: cell | (rank<<CBITS)
__device__ int    g_chist[NC];
__device__ int    g_cstart[NC + 2];
__device__ float2 g_cxy[NMAX];
__device__ int    g_cidx[NMAX];
__device__ int    g_total;
__device__ int    g_done_pack;
__device__ int    g_done_boxes;

__device__ __forceinline__ int cellc(float v) {
    int c = (int)floorf((v - ORG) * (1.0f / CELL));
    return min(max(c, 0), GX - 1);
}

// ---- warp-level sorted top-32 primitives (ascending) ----
__device__ __forceinline__ int warp_sort32(int v, int lane) {
    #pragma unroll
    for (int k = 2; k <= 32; k <<= 1) {
        #pragma unroll
        for (int j = k >> 1; j > 0; j >>= 1) {
            int o = __shfl_xor_sync(0xffffffffu, v, j);
            bool keepMin = (((lane & j) == 0) == ((lane & k) == 0));
            v = keepMin ? min(v, o) : max(v, o);
        }
    }
    return v;
}
__device__ __forceinline__ int warp_bmerge32(int v, int lane) {
    #pragma unroll
    for (int j = 16; j > 0; j >>= 1) {
        int o = __shfl_xor_sync(0xffffffffu, v, j);
        v = ((lane & j) == 0) ? min(v, o) : max(v, o);
    }
    return v;
}
__device__ __forceinline__ int warp_topk_merge(int a, int b, int lane) {
    int br = __shfl_sync(0xffffffffu, b, 31 - lane);
    return warp_bmerge32(min(a, br), lane);
}

// ---------------- K1: pack xy + hierarchical histogram + (last block) cell prefix ----------------
__global__ void __launch_bounds__(256) k_pack(const float* __restrict__ pts, int N) {
    __shared__ int sh_cnt[NC];
    __shared__ int sh_base[NC];
    __shared__ int s_last;
    int t = threadIdx.x;
    for (int c = t; c < NC; c += 256) sh_cnt[c] = 0;
    __syncthreads();

    int i0 = (blockIdx.x * 256 + t) * 4;
    float2 P[4];
    int cell[4], lr[4];
    bool val[4];
    if (i0 + 4 <= N) {
        const float4* p4 = (const float4*)(pts + (size_t)i0 * 5);
        float4 v[5];
        #pragma unroll
        for (int k = 0; k < 5; k++) v[k] = p4[k];
        const float* f = (const float*)v;
        #pragma unroll
        for (int k = 0; k < 4; k++) { P[k] = make_float2(f[5 * k], f[5 * k + 1]); val[k] = true; }
    } else {
        #pragma unroll
        for (int k = 0; k < 4; k++) {
            int i = i0 + k;
            val[k] = (i < N);
            P[k] = val[k] ? make_float2(pts[i * 5], pts[i * 5 + 1]) : make_float2(0.f, 0.f);
        }
    }
    #pragma unroll
    for (int k = 0; k < 4; k++) {
        if (val[k]) {
            int i = i0 + k;
            g_xy[i] = P[k];
            cell[k] = cellc(P[k].y) * GX + cellc(P[k].x);
            lr[k] = atomicAdd(&sh_cnt[cell[k]], 1);
        }
    }
    __syncthreads();
    for (int c = t; c < NC; c += 256) {
        int n = sh_cnt[c];
        sh_base[c] = n ? atomicAdd(&g_chist[c], n) : 0;
    }
    __syncthreads();
    #pragma unroll
    for (int k = 0; k < 4; k++)
        if (val[k]) g_cell[i0 + k] = cell[k] | ((sh_base[cell[k]] + lr[k]) << CBITS);

    // ---- last-done block: exclusive prefix over g_chist -> g_cstart, reset hist ----
    __threadfence();
    if (t == 0) s_last = (atomicAdd(&g_done_pack, 1) == (int)gridDim.x - 1);
    __syncthreads();
    if (!s_last) return;

    const int PER = (NC + 255) / 256;   // 6
    __shared__ int wofs[8];
    int lane = t & 31, wid = t >> 5;
    int loc[PER];
    int sum = 0;
    #pragma unroll
    for (int k = 0; k < PER; k++) {
        int idx = t * PER + k;
        int x = (idx < NC) ? g_chist[idx] : 0;
        loc[k] = sum;
        sum += x;
    }
    int inc = sum;
    #pragma unroll
    for (int off = 1; off < 32; off <<= 1) {
        int x = __shfl_up_sync(0xffffffffu, inc, off);
        if (lane >= off) inc += x;
    }
    int exc = inc - sum;
    if (lane == 31) wofs[wid] = inc;
    __syncthreads();
    if (wid == 0) {
        int w = (lane < 8) ? wofs[lane] : 0;
        int iw = w;
        #pragma unroll
        for (int off = 1; off < 8; off <<= 1) {
            int x = __shfl_up_sync(0xffffffffu, iw, off);
            if (lane >= off) iw += x;
        }
        if (lane < 8) wofs[lane] = iw - w;
    }
    __syncthreads();
    int base = exc + wofs[wid];
    #pragma unroll
    for (int k = 0; k < PER; k++) {
        int idx = t * PER + k;
        if (idx < NC) { g_cstart[idx] = base + loc[k]; g_chist[idx] = 0; }
    }
    if (t == 255) g_cstart[NC] = base + sum;
    if (t == 0) g_done_pack = 0;
}

// ---------------- K2: atomic-free scatter into cell lists + clear bitmask ----------------
__global__ void __launch_bounds__(256) k_fill(int N) {
    int i = blockIdx.x * 256 + threadIdx.x;
    if (i < NWORDS) g_bits[i] = 0u;     // cleared before k_boxes sets them
    if (i < N) {
        int pc = g_cell[i];
        int pos = g_cstart[pc & CMASK] + (pc >> CBITS);
        g_cxy[pos] = g_xy[i];
        g_cidx[pos] = i;
    }
}

// ---------------- K3: per-box selection + (last block) word-rank prefix ----------------
__global__ void __launch_bounds__(256) k_boxes(const float* __restrict__ boxes, int N) {
    int m = blockIdx.x;
    int tid = threadIdx.x;
    int lane = tid & 31, wid = tid >> 5;
    float bx = boxes[m * 7 + 0];
    float by = boxes[m * 7 + 1];
    float hx = __fmul_rn(boxes[m * 7 + 3], 0.5f);
    float hy = __fmul_rn(boxes[m * 7 + 4], 0.5f);
    float r  = __fmul_rn(sqrtf(__fadd_rn(__fmul_rn(hx, hx), __fmul_rn(hy, hy))), 1.1f);

    __shared__ int s_hit[HITCAP];
    __shared__ int s_ws[8][S];
    __shared__ int s_cnt, s_c;
    __shared__ int s_m[S], s_u[S];
    __shared__ int s_last;
    if (tid == 0) s_cnt = 0;
    __syncthreads();

    int cx0 = cellc(bx - r - 0.5f), cx1 = cellc(bx + r + 0.5f);
    int cy0 = cellc(by - r - 0.5f), cy1 = cellc(by + r + 0.5f);

    for (int cy = cy0; cy <= cy1; cy++) {
        int s0 = g_cstart[cy * GX + cx0];
        int s1 = g_cstart[cy * GX + cx1 + 1];
        for (int i = s0 + tid; i < s1; i += 256) {
            float2 p = g_cxy[i];
            float dx = __fadd_rn(bx, -p.x);
            float dy = __fadd_rn(by, -p.y);
            float d2 = __fadd_rn(__fmul_rn(dx, dx), __fmul_rn(dy, dy));
            if (sqrtf(d2) <= r) {
                int pos = atomicAdd(&s_cnt, 1);
                if (pos < HITCAP) s_hit[pos] = g_cidx[i];
            }
        }
    }
    __syncthreads();
    int cnt = s_cnt;

    if (cnt <= HITCAP) {
        int best = 0x7fffffff;
        bool first = true;
        for (int b = wid * 32; b < cnt; b += 256) {
            int idx = b + lane;
            int v = (idx < cnt) ? s_hit[idx] : 0x7fffffff;
            v = warp_sort32(v, lane);
            best = first ? v : warp_topk_merge(best, v, lane);
            first = false;
        }
        s_ws[wid][lane] = best;
        __syncthreads();
        if (wid == 0) {
            int nact = min((cnt + 31) >> 5, 8);
            int c = min(cnt, S);
            if (nact > 0) {
                int acc = s_ws[0][lane];
                for (int w = 1; w < nact; w++)
                    acc = warp_topk_merge(acc, s_ws[w][lane], lane);
                if (lane < c) s_m[lane] = acc;
            }
            if (lane == 0) s_c = c;
        }
    } else {
        if (tid < 32) {
            int got = 0;
            for (int base = 0; got < S && base < N; base += 32) {
                int i = base + lane;
                bool mem = false;
                if (i < N) {
                    float2 p = g_xy[i];
                    float dx = __fadd_rn(bx, -p.x);
                    float dy = __fadd_rn(by, -p.y);
                    float d2 = __fadd_rn(__fmul_rn(dx, dx), __fmul_rn(dy, dy));
                    mem = (sqrtf(d2) <= r);
                }
                unsigned bmask = __ballot_sync(0xffffffffu, mem);
                int before = __popc(bmask & ((1u << lane) - 1));
                if (mem && got + before < S) s_m[got + before] = i;
                got += __popc(bmask);
            }
            if (lane == 0) s_c = S;
        }
    }
    __syncthreads();
    int c = s_c;

    if (c < S) {
        if (tid < 32) {
            int need = S - c;
            int got = 0;
            for (int base = 0; got < need && base < N; base += 32) {
                int i = base + lane;
                bool nm = false;
                if (i < N) {
                    float2 p = g_xy[i];
                    float dx = __fadd_rn(bx, -p.x);
                    float dy = __fadd_rn(by, -p.y);
                    float d2 = __fadd_rn(__fmul_rn(dx, dx), __fmul_rn(dy, dy));
                    nm = !(sqrtf(d2) <= r);
                }
                unsigned bmask = __ballot_sync(0xffffffffu, nm);
                int before = __popc(bmask & ((1u << lane) - 1));
                if (nm && got + before < need) s_u[got + before] = i;
                got += __popc(bmask);
            }
        }
        __syncthreads();
    }

    if (tid < S) {
        int v = (tid < c) ? s_m[tid] : s_u[tid - c];
        g_sidx[m * S + tid] = v;
        atomicOr(&g_bits[v >> 5], 1u << (v & 31));
    }
    if (tid == 0) g_scount[m] = c;

    // ---- last-done block: exclusive popc prefix over g_bits -> g_wrank, g_total ----
    __threadfence();
    if (tid == 0) s_last = (atomicAdd(&g_done_boxes, 1) == (int)gridDim.x - 1);
    __syncthreads();
    if (!s_last) return;

    const int PER = (NWORDS + 255) / 256;   // 25
    __shared__ int wofs[8];
    int sum = 0;
    for (int k = 0; k < PER; k++) {
        int idx = tid * PER + k;
        if (idx < NWORDS) sum += __popc(g_bits[idx]);
    }
    int inc = sum;
    #pragma unroll
    for (int off = 1; off < 32; off <<= 1) {
        int x = __shfl_up_sync(0xffffffffu, inc, off);
        if (lane >= off) inc += x;
    }
    int exc = inc - sum;
    if (lane == 31) wofs[wid] = inc;
    __syncthreads();
    if (wid == 0) {
        int w = (lane < 8) ? wofs[lane] : 0;
        int iw = w;
        #pragma unroll
        for (int off = 1; off < 8; off <<= 1) {
            int x = __shfl_up_sync(0xffffffffu, iw, off);
            if (lane >= off) iw += x;
        }
        if (lane < 8) wofs[lane] = iw - w;
        if (lane == 7) g_total = iw;
    }
    __syncthreads();
    int run = exc + wofs[wid];
    for (int k = 0; k < PER; k++) {
        int idx = tid * PER + k;
        if (idx < NWORDS) {
            g_wrank[idx] = run;
            run += __popc(g_bits[idx]);
        }
    }
    if (tid == 0) g_done_boxes = 0;
}

// ---------------- K4: sampled_points + idx + qp scatter (ALL slots) & padding ----------------
__global__ void k_out(const float* __restrict__ pts, float* __restrict__ outp,
                      float* __restrict__ outi, float* __restrict__ qp, int M) {
    int t = blockIdx.x * blockDim.x + threadIdx.x;
    if (t < M * S) {
        int m = t >> 5, j = t & 31;
        int c = g_scount[m];
        int p = g_sidx[t];

        // rank valid for every sidx entry (member AND filler): bits set for all 32 slots
        int w = p >> 5, bit = p & 31;
        unsigned word = g_bits[w];
        int rank = g_wrank[w] + __popc(word & ((1u << bit) - 1u));

        float v0 = pts[p * 5 + 0], v1 = pts[p * 5 + 1], v2 = pts[p * 5 + 2];
        float v3 = pts[p * 5 + 3], v4 = pts[p * 5 + 4];

        // qp scatter for ALL slots (fillers included); duplicate writers store identical bytes
        qp[(size_t)rank * 5 + 0] = v0; qp[(size_t)rank * 5 + 1] = v1;
        qp[(size_t)rank * 5 + 2] = v2; qp[(size_t)rank * 5 + 3] = v3;
        qp[(size_t)rank * 5 + 4] = v4;

        bool msk = (j < c);
        outi[t] = msk ? (float)rank : 0.0f;
        outp[t * 5 + 0] = msk ? v0 : 0.0f;
        outp[t * 5 + 1] = msk ? v1 : 0.0f;
        outp[t * 5 + 2] = msk ? v2 : 0.0f;
        outp[t * 5 + 3] = msk ? v3 : 0.0f;
        outp[t * 5 + 4] = msk ? v4 : 0.0f;

        if (t >= g_total) {
            #pragma unroll
            for (int cc = 0; cc < 5; cc++) qp[t * 5 + cc] = pts[cc];
        }
    }
}

// ---------------- launch ----------------
extern "C" void kernel_launch(void* const* d_in, const int* in_sizes, int n_in,
                              void* d_out, int out_size) {
    const float* pts   = (const float*)d_in[0];
    const float* boxes = (const float*)d_in[1];
    int N = in_sizes[0] / 5;
    int M = in_sizes[1] / 7;
    if (N > NMAX) N = NMAX;
    if (M > MMAX) M = MMAX;

    float* out  = (float*)d_out;
    float* outp = out;                            // sampled_points [M*S*5]
    float* outi = out + (size_t)M * S * 5;        // idx            [M*S]
    float* qp   = outi + (size_t)M * S;           // query_points   [M*S*5]

    k_pack<<<(N + 1023) / 1024, 256>>>(pts, N);
    k_fill<<<(N + 255) / 256, 256>>>(N);
    k_boxes<<<M, 256>>>(boxes, N);
    k_out<<<(M * S + 255) / 256, 256>>>(pts, outp, outi, qp, M);
}

// round 11
// speedup vs baseline: 1.0584x; 1.0584x over previous
#include <cuda_runtime.h>

#define S 32
#define NMAX 204800
#define MMAX 2048

#define GX 38
#define NC (GX * GX)
#define CELL 4.0f
#define ORG (-76.0f)
#define CBITS 11
#define CMASK ((1 << CBITS) - 1)
#define HITCAP 2048
#define NWORDS ((NMAX + 31) / 32)
#define MARGIN 0.05f

// ---------------- scratch (no allocations allowed) ----------------
__device__ float2 g_xy[NMAX];
__device__ unsigned g_bits[NWORDS];   // flag bitmask (zero-init; k_fill re-clears)
__device__ int    g_wrank[NWORDS];    // exclusive popc prefix per word
__device__ int    g_sidx[MMAX * S];
__device__ int    g_scount[MMAX];
__device__ int    g_cell[NMAX];       // packed: cell | (rank<<CBITS)
__device__ int    g_chist[NC];
__device__ int    g_cstart[NC + 2];
__device__ float2 g_cxy[NMAX];
__device__ int    g_cidx[NMAX];
__device__ int    g_total;
__device__ int    g_done_pack;
__device__ int    g_done_boxes;

__device__ __forceinline__ int cellc(float v) {
    int c = (int)floorf((v - ORG) * (1.0f / CELL));
    return min(max(c, 0), GX - 1);
}

// ---- warp-level sorted top-32 primitives (ascending) ----
__device__ __forceinline__ int warp_sort32(int v, int lane) {
    #pragma unroll
    for (int k = 2; k <= 32; k <<= 1) {
        #pragma unroll
        for (int j = k >> 1; j > 0; j >>= 1) {
            int o = __shfl_xor_sync(0xffffffffu, v, j);
            bool keepMin = (((lane & j) == 0) == ((lane & k) == 0));
            v = keepMin ? min(v, o) : max(v, o);
        }
    }
    return v;
}
__device__ __forceinline__ int warp_bmerge32(int v, int lane) {
    #pragma unroll
    for (int j = 16; j > 0; j >>= 1) {
        int o = __shfl_xor_sync(0xffffffffu, v, j);
        v = ((lane & j) == 0) ? min(v, o) : max(v, o);
    }
    return v;
}
__device__ __forceinline__ int warp_topk_merge(int a, int b, int lane) {
    int br = __shfl_sync(0xffffffffu, b, 31 - lane);
    return warp_bmerge32(min(a, br), lane);
}

// ---------------- K1: pack xy + hierarchical histogram + (last block) cell prefix ----------------
__global__ void __launch_bounds__(256) k_pack(const float* __restrict__ pts, int N) {
    __shared__ int sh_cnt[NC];
    __shared__ int sh_base[NC];
    __shared__ int s_last;
    int t = threadIdx.x;
    for (int c = t; c < NC; c += 256) sh_cnt[c] = 0;
    __syncthreads();

    int i0 = (blockIdx.x * 256 + t) * 4;
    float2 P[4];
    int cell[4], lr[4];
    bool val[4];
    if (i0 + 4 <= N) {
        const float4* p4 = (const float4*)(pts + (size_t)i0 * 5);
        float4 v[5];
        #pragma unroll
        for (int k = 0; k < 5; k++) v[k] = p4[k];
        const float* f = (const float*)v;
        #pragma unroll
        for (int k = 0; k < 4; k++) { P[k] = make_float2(f[5 * k], f[5 * k + 1]); val[k] = true; }
    } else {
        #pragma unroll
        for (int k = 0; k < 4; k++) {
            int i = i0 + k;
            val[k] = (i < N);
            P[k] = val[k] ? make_float2(pts[i * 5], pts[i * 5 + 1]) : make_float2(0.f, 0.f);
        }
    }
    #pragma unroll
    for (int k = 0; k < 4; k++) {
        if (val[k]) {
            int i = i0 + k;
            g_xy[i] = P[k];
            cell[k] = cellc(P[k].y) * GX + cellc(P[k].x);
            lr[k] = atomicAdd(&sh_cnt[cell[k]], 1);
        }
    }
    __syncthreads();
    for (int c = t; c < NC; c += 256) {
        int n = sh_cnt[c];
        sh_base[c] = n ? atomicAdd(&g_chist[c], n) : 0;
    }
    __syncthreads();
    #pragma unroll
    for (int k = 0; k < 4; k++)
        if (val[k]) g_cell[i0 + k] = cell[k] | ((sh_base[cell[k]] + lr[k]) << CBITS);

    // ---- last-done block: exclusive prefix over g_chist -> g_cstart, reset hist ----
    __threadfence();
    if (t == 0) s_last = (atomicAdd(&g_done_pack, 1) == (int)gridDim.x - 1);
    __syncthreads();
    if (!s_last) return;

    const int PER = (NC + 255) / 256;   // 6
    __shared__ int wofs[8];
    int lane = t & 31, wid = t >> 5;
    int loc[PER];
    int sum = 0;
    #pragma unroll
    for (int k = 0; k < PER; k++) {
        int idx = t * PER + k;
        int x = (idx < NC) ? g_chist[idx] : 0;
        loc[k] = sum;
        sum += x;
    }
    int inc = sum;
    #pragma unroll
    for (int off = 1; off < 32; off <<= 1) {
        int x = __shfl_up_sync(0xffffffffu, inc, off);
        if (lane >= off) inc += x;
    }
    int exc = inc - sum;
    if (lane == 31) wofs[wid] = inc;
    __syncthreads();
    if (wid == 0) {
        int w = (lane < 8) ? wofs[lane] : 0;
        int iw = w;
        #pragma unroll
        for (int off = 1; off < 8; off <<= 1) {
            int x = __shfl_up_sync(0xffffffffu, iw, off);
            if (lane >= off) iw += x;
        }
        if (lane < 8) wofs[lane] = iw - w;
    }
    __syncthreads();
    int base = exc + wofs[wid];
    #pragma unroll
    for (int k = 0; k < PER; k++) {
        int idx = t * PER + k;
        if (idx < NC) { g_cstart[idx] = base + loc[k]; g_chist[idx] = 0; }
    }
    if (t == 255) g_cstart[NC] = base + sum;
    if (t == 0) g_done_pack = 0;
}

// ---------------- K2: atomic-free scatter into cell lists + clear bitmask ----------------
__global__ void __launch_bounds__(256) k_fill(int N) {
    int i = blockIdx.x * 256 + threadIdx.x;
    if (i < NWORDS) g_bits[i] = 0u;     // cleared before k_boxes sets them
    if (i < N) {
        int pc = g_cell[i];
        int pos = g_cstart[pc & CMASK] + (pc >> CBITS);
        g_cxy[pos] = g_xy[i];
        g_cidx[pos] = i;
    }
}

// ---------------- K3: per-box selection + (last block) word-rank prefix ----------------
__global__ void __launch_bounds__(256) k_boxes(const float* __restrict__ boxes, int N) {
    int m = blockIdx.x;
    int tid = threadIdx.x;
    int lane = tid & 31, wid = tid >> 5;
    float bx = boxes[m * 7 + 0];
    float by = boxes[m * 7 + 1];
    float hx = __fmul_rn(boxes[m * 7 + 3], 0.5f);
    float hy = __fmul_rn(boxes[m * 7 + 4], 0.5f);
    float r  = __fmul_rn(sqrtf(__fadd_rn(__fmul_rn(hx, hx), __fmul_rn(hy, hy))), 1.1f);

    __shared__ int s_hit[HITCAP];
    __shared__ int s_ws[8][S];
    __shared__ int s_cnt, s_c;
    __shared__ int s_m[S], s_u[S];
    __shared__ int s_last;
    if (tid == 0) s_cnt = 0;
    __syncthreads();

    int cx0 = cellc(bx - r - MARGIN), cx1 = cellc(bx + r + MARGIN);
    int cy0 = cellc(by - r - MARGIN), cy1 = cellc(by + r + MARGIN);

    for (int cy = cy0; cy <= cy1; cy++) {
        int s0 = g_cstart[cy * GX + cx0];
        int s1 = g_cstart[cy * GX + cx1 + 1];
        for (int i = s0 + tid; i < s1; i += 256) {
            float2 p = g_cxy[i];
            float dx = __fadd_rn(bx, -p.x);
            float dy = __fadd_rn(by, -p.y);
            float d2 = __fadd_rn(__fmul_rn(dx, dx), __fmul_rn(dy, dy));
            if (sqrtf(d2) <= r) {
                int pos = atomicAdd(&s_cnt, 1);
                if (pos < HITCAP) s_hit[pos] = g_cidx[i];
            }
        }
    }
    __syncthreads();
    int cnt = s_cnt;

    if (cnt <= HITCAP) {
        int best = 0x7fffffff;
        bool first = true;
        for (int b = wid * 32; b < cnt; b += 256) {
            int idx = b + lane;
            int v = (idx < cnt) ? s_hit[idx] : 0x7fffffff;
            v = warp_sort32(v, lane);
            best = first ? v : warp_topk_merge(best, v, lane);
            first = false;
        }
        s_ws[wid][lane] = best;
        __syncthreads();
        if (wid == 0) {
            int nact = min((cnt + 31) >> 5, 8);
            int c = min(cnt, S);
            if (nact > 0) {
                int acc = s_ws[0][lane];
                for (int w = 1; w < nact; w++)
                    acc = warp_topk_merge(acc, s_ws[w][lane], lane);
                if (lane < c) s_m[lane] = acc;
            }
            if (lane == 0) s_c = c;
        }
    } else {
        if (tid < 32) {
            int got = 0;
            for (int base = 0; got < S && base < N; base += 32) {
                int i = base + lane;
                bool mem = false;
                if (i < N) {
                    float2 p = g_xy[i];
                    float dx = __fadd_rn(bx, -p.x);
                    float dy = __fadd_rn(by, -p.y);
                    float d2 = __fadd_rn(__fmul_rn(dx, dx), __fmul_rn(dy, dy));
                    mem = (sqrtf(d2) <= r);
                }
                unsigned bmask = __ballot_sync(0xffffffffu, mem);
                int before = __popc(bmask & ((1u << lane) - 1));
                if (mem && got + before < S) s_m[got + before] = i;
                got += __popc(bmask);
            }
            if (lane == 0) s_c = S;
        }
    }
    __syncthreads();
    int c = s_c;

    if (c < S) {
        if (tid < 32) {
            int need = S - c;
            int got = 0;
            for (int base = 0; got < need && base < N; base += 32) {
                int i = base + lane;
                bool nm = false;
                if (i < N) {
                    float2 p = g_xy[i];
                    float dx = __fadd_rn(bx, -p.x);
                    float dy = __fadd_rn(by, -p.y);
                    float d2 = __fadd_rn(__fmul_rn(dx, dx), __fmul_rn(dy, dy));
                    nm = !(sqrtf(d2) <= r);
                }
                unsigned bmask = __ballot_sync(0xffffffffu, nm);
                int before = __popc(bmask & ((1u << lane) - 1));
                if (nm && got + before < need) s_u[got + before] = i;
                got += __popc(bmask);
            }
        }
        __syncthreads();
    }

    if (tid < S) {
        int v = (tid < c) ? s_m[tid] : s_u[tid - c];
        g_sidx[m * S + tid] = v;
        atomicOr(&g_bits[v >> 5], 1u << (v & 31));
    }
    if (tid == 0) g_scount[m] = c;

    // ---- last-done block: exclusive popc prefix over g_bits -> g_wrank, g_total ----
    __threadfence();
    if (tid == 0) s_last = (atomicAdd(&g_done_boxes, 1) == (int)gridDim.x - 1);
    __syncthreads();
    if (!s_last) return;

    const int PER = (NWORDS + 255) / 256;   // 25
    __shared__ int wofs[8];
    int sum = 0;
    for (int k = 0; k < PER; k++) {
        int idx = tid * PER + k;
        if (idx < NWORDS) sum += __popc(g_bits[idx]);
    }
    int inc = sum;
    #pragma unroll
    for (int off = 1; off < 32; off <<= 1) {
        int x = __shfl_up_sync(0xffffffffu, inc, off);
        if (lane >= off) inc += x;
    }
    int exc = inc - sum;
    if (lane == 31) wofs[wid] = inc;
    __syncthreads();
    if (wid == 0) {
        int w = (lane < 8) ? wofs[lane] : 0;
        int iw = w;
        #pragma unroll
        for (int off = 1; off < 8; off <<= 1) {
            int x = __shfl_up_sync(0xffffffffu, iw, off);
            if (lane >= off) iw += x;
        }
        if (lane < 8) wofs[lane] = iw - w;
        if (lane == 7) g_total = iw;
    }
    __syncthreads();
    int run = exc + wofs[wid];
    for (int k = 0; k < PER; k++) {
        int idx = tid * PER + k;
        if (idx < NWORDS) {
            g_wrank[idx] = run;
            run += __popc(g_bits[idx]);
        }
    }
    if (tid == 0) g_done_boxes = 0;
}

// ---------------- K4: component-parallel outputs (1 thread per slot*component) ----------------
__global__ void __launch_bounds__(256) k_out(const float* __restrict__ pts,
                                             float* __restrict__ outp,
                                             float* __restrict__ outi,
                                             float* __restrict__ qp, int M) {
    int idx = blockIdx.x * 256 + threadIdx.x;   // over M*S*5
    if (idx >= M * S * 5) return;
    int t = idx / 5, cc = idx - t * 5;
    int m = t >> 5, j = t & 31;
    int c = g_scount[m];
    int p = g_sidx[t];

    // rank valid for every sidx entry (member AND filler): bits set for all 32 slots
    int w = p >> 5, bit = p & 31;
    unsigned word = g_bits[w];
    int rank = g_wrank[w] + __popc(word & ((1u << bit) - 1u));

    float v = pts[p * 5 + cc];

    // qp scatter for ALL slots (fillers included); duplicate writers store identical bytes
    qp[(size_t)rank * 5 + cc] = v;

    bool msk = (j < c);
    outp[idx] = msk ? v : 0.0f;
    if (cc == 0) outi[t] = msk ? (float)rank : 0.0f;

    if (t >= g_total) qp[(size_t)t * 5 + cc] = pts[cc];
}

// ---------------- launch ----------------
extern "C" void kernel_launch(void* const* d_in, const int* in_sizes, int n_in,
                              void* d_out, int out_size) {
    const float* pts   = (const float*)d_in[0];
    const float* boxes = (const float*)d_in[1];
    int N = in_sizes[0] / 5;
    int M = in_sizes[1] / 7;
    if (N > NMAX) N = NMAX;
    if (M > MMAX) M = MMAX;

    float* out  = (float*)d_out;
    float* outp = out;                            // sampled_points [M*S*5]
    float* outi = out + (size_t)M * S * 5;        // idx            [M*S]
    float* qp   = outi + (size_t)M * S;           // query_points   [M*S*5]

    k_pack<<<(N + 1023) / 1024, 256>>>(pts, N);
    k_fill<<<(N + 255) / 256, 256>>>(N);
    k_boxes<<<M, 256>>>(boxes, N);
    k_out<<<(M * S * 5 + 255) / 256, 256>>>(pts, outp, outi, qp, M);
}